// round 7
// baseline (speedup 1.0000x reference)
#include <cuda_runtime.h>
#include <cuda_bf16.h>

// B=16384, NNEG=10, D=8, E=64, N_ENT=500000.
// score(x) = exp( exp(pair_w[0]) * 0.5 * ( ||sum_d e_d||^2 - sum_d ||e_d||^2 ) + c )
//
// FOUR scores per warp: half-warp h owns scores s0 = 4*warp + h and
// s1 = s0 + 2. Lane (l&15) owns float4 dims [4*(l&15) .. +3].
// All 16 row-gathers (8 per score) hoisted -> up to 8KB outstanding per
// warp. Gathers use __ldcg (L2-only): random rows never hit L1, so skip
// L1 allocation entirely. Total L2 delivery = 1.44M rows * 256B = 369MB,
// which is the information-theoretic minimum; this kernel rides the
// chip-wide LTS delivery cap.

#define D_DIM 8
#define E_DIM 64

__global__ __launch_bounds__(256) void APE_61555471286335_kernel(
    const int*   __restrict__ pos_x,     // [B, 8]
    const int*   __restrict__ neg_x,     // [B*NNEG, 8]
    const float* __restrict__ emb,       // [N_ENT, 64]
    const float* __restrict__ pair_w,    // [28]
    const float* __restrict__ cvec,      // [1]
    float*       __restrict__ out,       // [B + B*NNEG]
    int n_scores, int B)
{
    int warp  = (blockIdx.x * blockDim.x + threadIdx.x) >> 5;
    int lane  = threadIdx.x & 31;
    int half  = lane >> 4;        // half-warp id (0/1)
    int laneh = lane & 15;        // lane within half-warp

    int s0 = 4 * warp + half;     // first score of this half-warp
    int s1 = s0 + 2;              // second score
    bool a0 = (s0 < n_scores);
    bool a1 = (s1 < n_scores);
    int c0 = a0 ? s0 : 0;
    int c1 = a1 ? s1 : 0;

    // half-warp loads 16 indices: lanes 0-7 -> s0's 8 idx, lanes 8-15 -> s1's
    int sc   = (laneh < D_DIM) ? c0 : c1;
    int dd   = laneh & 7;
    const int* idxp = (sc < B) ? (pos_x + sc * D_DIM)
                               : (neg_x + (size_t)(sc - B) * D_DIM);
    int myidx = __ldg(idxp + dd);

    // hoist all 16 gathers (interleaved across the two scores)
    float4 v0[D_DIM], v1[D_DIM];
    #pragma unroll
    for (int d = 0; d < D_DIM; d++) {
        int r0 = __shfl_sync(0xffffffffu, myidx, (half << 4) + d);
        int r1 = __shfl_sync(0xffffffffu, myidx, (half << 4) + 8 + d);
        v0[d] = __ldcg(reinterpret_cast<const float4*>(
                           emb + (size_t)r0 * E_DIM) + laneh);
        v1[d] = __ldcg(reinterpret_cast<const float4*>(
                           emb + (size_t)r1 * E_DIM) + laneh);
    }

    float sx0 = 0.f, sy0 = 0.f, sz0 = 0.f, sw0 = 0.f, sq0 = 0.f;
    float sx1 = 0.f, sy1 = 0.f, sz1 = 0.f, sw1 = 0.f, sq1 = 0.f;
    #pragma unroll
    for (int d = 0; d < D_DIM; d++) {
        sx0 += v0[d].x; sy0 += v0[d].y; sz0 += v0[d].z; sw0 += v0[d].w;
        sq0 += v0[d].x * v0[d].x + v0[d].y * v0[d].y
             + v0[d].z * v0[d].z + v0[d].w * v0[d].w;
        sx1 += v1[d].x; sy1 += v1[d].y; sz1 += v1[d].z; sw1 += v1[d].w;
        sq1 += v1[d].x * v1[d].x + v1[d].y * v1[d].y
             + v1[d].z * v1[d].z + v1[d].w * v1[d].w;
    }

    float val0 = sx0 * sx0 + sy0 * sy0 + sz0 * sz0 + sw0 * sw0 - sq0;
    float val1 = sx1 * sx1 + sy1 * sy1 + sz1 * sz1 + sw1 * sw1 - sq1;
    #pragma unroll
    for (int off = 8; off; off >>= 1) {
        val0 += __shfl_xor_sync(0xffffffffu, val0, off);
        val1 += __shfl_xor_sync(0xffffffffu, val1, off);
    }

    if (laneh == 0) {
        float w0 = expf(pair_w[0]);
        float cc = cvec[0];
        if (a0) out[s0] = expf(0.5f * val0 * w0 + cc);
        if (a1) out[s1] = expf(0.5f * val1 * w0 + cc);
    }
}

extern "C" void kernel_launch(void* const* d_in, const int* in_sizes, int n_in,
                              void* d_out, int out_size) {
    const int*   pos_x  = (const int*)  d_in[0];
    const int*   neg_x  = (const int*)  d_in[1];
    const float* emb    = (const float*)d_in[2];
    const float* pair_w = (const float*)d_in[3];
    const float* cvec   = (const float*)d_in[4];
    float*       out    = (float*)d_out;

    int B        = in_sizes[0] / D_DIM;              // 16384
    int n_neg    = in_sizes[1] / D_DIM;              // B*NNEG
    int n_scores = B + n_neg;                        // 180224

    int threads = 256;                               // 8 warps = 32 scores/block
    int scores_per_block = (threads / 32) * 4;
    int blocks = (n_scores + scores_per_block - 1) / scores_per_block;

    APE_61555471286335_kernel<<<blocks, threads>>>(
        pos_x, neg_x, emb, pair_w, cvec, out, n_scores, B);
}

// round 8
// speedup vs baseline: 1.1944x; 1.1944x over previous
#include <cuda_runtime.h>
#include <cuda_bf16.h>

// B=16384, NNEG=10, D=8, E=64, N_ENT=500000.
// score(x) = exp( exp(pair_w[0]) * 0.5 * ( ||sum_d e_d||^2 - sum_d ||e_d||^2 ) + c )
//
// FOUR scores per warp: half-warp h owns scores s0 = 4*warp + h and
// s1 = s0 + 2. Lane (l&15) owns float4 dims [4*(l&15) .. +3].
// All 16 row-gathers (8 per score) hoisted -> up to 8KB outstanding per
// warp. Gathers use __ldcg (L2-only): random rows never hit L1, so skip
// L1 allocation entirely. Total L2 delivery = 1.44M rows * 256B = 369MB,
// which is the information-theoretic minimum; this kernel rides the
// chip-wide LTS delivery cap.

#define D_DIM 8
#define E_DIM 64

__global__ __launch_bounds__(256) void APE_61555471286335_kernel(
    const int*   __restrict__ pos_x,     // [B, 8]
    const int*   __restrict__ neg_x,     // [B*NNEG, 8]
    const float* __restrict__ emb,       // [N_ENT, 64]
    const float* __restrict__ pair_w,    // [28]
    const float* __restrict__ cvec,      // [1]
    float*       __restrict__ out,       // [B + B*NNEG]
    int n_scores, int B)
{
    int warp  = (blockIdx.x * blockDim.x + threadIdx.x) >> 5;
    int lane  = threadIdx.x & 31;
    int half  = lane >> 4;        // half-warp id (0/1)
    int laneh = lane & 15;        // lane within half-warp

    int s0 = 4 * warp + half;     // first score of this half-warp
    int s1 = s0 + 2;              // second score
    bool a0 = (s0 < n_scores);
    bool a1 = (s1 < n_scores);
    int c0 = a0 ? s0 : 0;
    int c1 = a1 ? s1 : 0;

    // half-warp loads 16 indices: lanes 0-7 -> s0's 8 idx, lanes 8-15 -> s1's
    int sc   = (laneh < D_DIM) ? c0 : c1;
    int dd   = laneh & 7;
    const int* idxp = (sc < B) ? (pos_x + sc * D_DIM)
                               : (neg_x + (size_t)(sc - B) * D_DIM);
    int myidx = __ldg(idxp + dd);

    // hoist all 16 gathers (interleaved across the two scores)
    float4 v0[D_DIM], v1[D_DIM];
    #pragma unroll
    for (int d = 0; d < D_DIM; d++) {
        int r0 = __shfl_sync(0xffffffffu, myidx, (half << 4) + d);
        int r1 = __shfl_sync(0xffffffffu, myidx, (half << 4) + 8 + d);
        v0[d] = __ldcg(reinterpret_cast<const float4*>(
                           emb + (size_t)r0 * E_DIM) + laneh);
        v1[d] = __ldcg(reinterpret_cast<const float4*>(
                           emb + (size_t)r1 * E_DIM) + laneh);
    }

    float sx0 = 0.f, sy0 = 0.f, sz0 = 0.f, sw0 = 0.f, sq0 = 0.f;
    float sx1 = 0.f, sy1 = 0.f, sz1 = 0.f, sw1 = 0.f, sq1 = 0.f;
    #pragma unroll
    for (int d = 0; d < D_DIM; d++) {
        sx0 += v0[d].x; sy0 += v0[d].y; sz0 += v0[d].z; sw0 += v0[d].w;
        sq0 += v0[d].x * v0[d].x + v0[d].y * v0[d].y
             + v0[d].z * v0[d].z + v0[d].w * v0[d].w;
        sx1 += v1[d].x; sy1 += v1[d].y; sz1 += v1[d].z; sw1 += v1[d].w;
        sq1 += v1[d].x * v1[d].x + v1[d].y * v1[d].y
             + v1[d].z * v1[d].z + v1[d].w * v1[d].w;
    }

    float val0 = sx0 * sx0 + sy0 * sy0 + sz0 * sz0 + sw0 * sw0 - sq0;
    float val1 = sx1 * sx1 + sy1 * sy1 + sz1 * sz1 + sw1 * sw1 - sq1;
    #pragma unroll
    for (int off = 8; off; off >>= 1) {
        val0 += __shfl_xor_sync(0xffffffffu, val0, off);
        val1 += __shfl_xor_sync(0xffffffffu, val1, off);
    }

    if (laneh == 0) {
        float w0 = expf(pair_w[0]);
        float cc = cvec[0];
        if (a0) out[s0] = expf(0.5f * val0 * w0 + cc);
        if (a1) out[s1] = expf(0.5f * val1 * w0 + cc);
    }
}

extern "C" void kernel_launch(void* const* d_in, const int* in_sizes, int n_in,
                              void* d_out, int out_size) {
    const int*   pos_x  = (const int*)  d_in[0];
    const int*   neg_x  = (const int*)  d_in[1];
    const float* emb    = (const float*)d_in[2];
    const float* pair_w = (const float*)d_in[3];
    const float* cvec   = (const float*)d_in[4];
    float*       out    = (float*)d_out;

    int B        = in_sizes[0] / D_DIM;              // 16384
    int n_neg    = in_sizes[1] / D_DIM;              // B*NNEG
    int n_scores = B + n_neg;                        // 180224

    int threads = 256;                               // 8 warps = 32 scores/block
    int scores_per_block = (threads / 32) * 4;
    int blocks = (n_scores + scores_per_block - 1) / scores_per_block;

    APE_61555471286335_kernel<<<blocks, threads>>>(
        pos_x, neg_x, emb, pair_w, cvec, out, n_scores, B);
}